// round 15
// baseline (speedup 1.0000x reference)
#include <cuda_runtime.h>
#include <cuda_bf16.h>
#include <cstdint>

// HyperLayer multilinear gather/scatter, factorized:
//   G = bilinear gather from x over (dim0,dim1); y[o2,o3] += v*G*w2*w3 over 4 combos.
// R14: fully branchless pair gather/scatter (aligned float2 + predicated second
// op, no BSSY) so ptxas can batch loads; 4 samples/thread for MLP.

#define DIM 1024

__global__ void hyper_zero_kernel(float4* __restrict__ y, int n4) {
    int i = blockIdx.x * blockDim.x + threadIdx.x;
    if (i < n4) y[i] = make_float4(0.f, 0.f, 0.f, 0.f);
}

__device__ __forceinline__ float2 ldg2(const float* p) {
    return __ldg((const float2*)p);
}

// Branchless gather of base[i], base[j] where j==i or j==i+1.
// One aligned float2 load always; predicated second load only when the pair
// straddles an alignment boundary (odd i with j==i+1).
__device__ __forceinline__ void gather_pair(const float* __restrict__ base,
                                            int i, int j, float& a, float& b) {
    const float2 p = ldg2(base + (i & ~1));
    const bool odd  = (i & 1);
    const bool sec  = odd && (j != i);      // need element at j=i+1 (even)
    a = odd ? p.y : p.x;
    float qx = 0.f;
    if (sec) qx = ldg2(base + j).x;         // predicated, j aligned
    b = sec ? qx : ((j == i) ? a : p.y);
}

// Branchless scatter-add va->base[i], vb->base[j] (j==i or j==i+1).
// Always one aligned float2 atomic (untouched lane gets +0.0f, exact no-op);
// predicated second atomic only for odd i with distinct j.
// j==i collapses to a single add of (va+vb) == reference double-count.
__device__ __forceinline__ void scatter_pair(float* __restrict__ base,
                                             int i, int j, float va, float vb) {
    const bool odd  = (i & 1);
    const bool same = (j == i);
    const float s = va + vb;
    float2 first;
    if (!odd) first = same ? make_float2(s, 0.f) : make_float2(va, vb);
    else      first = make_float2(0.f, same ? s : va);
    atomicAdd((float2*)(base + (i & ~1)), first);
    if (odd && !same)
        atomicAdd((float2*)(base + i + 1), make_float2(vb, 0.f));
}

__device__ __forceinline__ void process_sample(const float* __restrict__ x,
                                               float4 r, float v,
                                               float* __restrict__ y) {
    // wf = 1-(r-floor), wc = 1-(ceil-r); matches reference including the
    // frac==0 case (floor==ceil, both weights 1 -> double count).
    float f0 = floorf(r.x), c0 = ceilf(r.x);
    float wf0 = 1.0f - (r.x - f0), wc0 = 1.0f - (c0 - r.x);
    float f1 = floorf(r.y), c1 = ceilf(r.y);
    float wf1 = 1.0f - (r.y - f1), wc1 = 1.0f - (c1 - r.y);
    float f2 = floorf(r.z), c2 = ceilf(r.z);
    float wf2 = 1.0f - (r.z - f2), wc2 = 1.0f - (c2 - r.z);
    float f3 = floorf(r.w), c3 = ceilf(r.w);
    float wf3 = 1.0f - (r.w - f3), wc3 = 1.0f - (c3 - r.w);

    int if0 = (int)f0, ic0 = (int)c0;
    int if1 = (int)f1, ic1 = (int)c1;
    int if2 = (int)f2, ic2 = (int)c2;
    int if3 = (int)f3, ic3 = (int)c3;

    float xff, xfc, xcf, xcc;
    gather_pair(x + (long)if0 * DIM, if1, ic1, xff, xfc);
    gather_pair(x + (long)ic0 * DIM, if1, ic1, xcf, xcc);

    float G = wf0 * (wf1 * xff + wc1 * xfc)
            + wc0 * (wf1 * xcf + wc1 * xcc);
    float gv = G * v;

    scatter_pair(y + (long)if2 * DIM, if3, ic3, gv * wf2 * wf3, gv * wf2 * wc3);
    scatter_pair(y + (long)ic2 * DIM, if3, ic3, gv * wc2 * wf3, gv * wc2 * wc3);
}

#define SPT 4   // samples per thread

__global__ void __launch_bounds__(256) hyper_main_kernel(
    const float* __restrict__ x,
    const float4* __restrict__ ri,   // [N] of (r0,r1,r2,r3)
    const float* __restrict__ rv,    // [N]
    float* __restrict__ y,
    int N, int T)                    // T = threads doing work; samples tid + k*T
{
    int tid = blockIdx.x * blockDim.x + threadIdx.x;
    if (tid >= T) return;

    float4 r[SPT];
    float  v[SPT];
    bool   has[SPT];

    // Batch the index/value loads up front for MLP.
    #pragma unroll
    for (int k = 0; k < SPT; k++) {
        int n = tid + k * T;
        has[k] = (n < N);
        if (has[k]) { r[k] = ri[n]; v[k] = rv[n]; }
    }

    #pragma unroll
    for (int k = 0; k < SPT; k++) {
        if (has[k]) process_sample(x, r[k], v[k], y);
    }
}

extern "C" void kernel_launch(void* const* d_in, const int* in_sizes, int n_in,
                              void* d_out, int out_size) {
    const float*  x  = (const float*)d_in[0];   // 1024*1024
    const float4* ri = (const float4*)d_in[1];  // N x float4
    const float*  rv = (const float*)d_in[2];   // N
    float*        y  = (float*)d_out;           // 1024*1024

    int N = in_sizes[2];

    int n4 = out_size / 4;
    hyper_zero_kernel<<<(n4 + 255) / 256, 256>>>((float4*)y, n4);

    int T = (N + SPT - 1) / SPT;         // SPT samples per thread
    int blocks = (T + 255) / 256;
    hyper_main_kernel<<<blocks, 256>>>(x, ri, rv, y, N, T);
}

// round 16
// speedup vs baseline: 1.0135x; 1.0135x over previous
#include <cuda_runtime.h>
#include <cuda_bf16.h>
#include <cstdint>

// HyperLayer multilinear gather/scatter, factorized:
//   G = bilinear gather from x over (dim0,dim1); y[o2,o3] += v*G*w2*w3 over 4 combos.
// R14: fully branchless pair gather/scatter (aligned float2 + predicated second
// op, no BSSY) so ptxas can batch loads; 4 samples/thread for MLP.

#define DIM 1024

__global__ void hyper_zero_kernel(float4* __restrict__ y, int n4) {
    int i = blockIdx.x * blockDim.x + threadIdx.x;
    if (i < n4) y[i] = make_float4(0.f, 0.f, 0.f, 0.f);
}

__device__ __forceinline__ float2 ldg2(const float* p) {
    return __ldg((const float2*)p);
}

// Branchless gather of base[i], base[j] where j==i or j==i+1.
// One aligned float2 load always; predicated second load only when the pair
// straddles an alignment boundary (odd i with j==i+1).
__device__ __forceinline__ void gather_pair(const float* __restrict__ base,
                                            int i, int j, float& a, float& b) {
    const float2 p = ldg2(base + (i & ~1));
    const bool odd  = (i & 1);
    const bool sec  = odd && (j != i);      // need element at j=i+1 (even)
    a = odd ? p.y : p.x;
    float qx = 0.f;
    if (sec) qx = ldg2(base + j).x;         // predicated, j aligned
    b = sec ? qx : ((j == i) ? a : p.y);
}

// Branchless scatter-add va->base[i], vb->base[j] (j==i or j==i+1).
// Always one aligned float2 atomic (untouched lane gets +0.0f, exact no-op);
// predicated second atomic only for odd i with distinct j.
// j==i collapses to a single add of (va+vb) == reference double-count.
__device__ __forceinline__ void scatter_pair(float* __restrict__ base,
                                             int i, int j, float va, float vb) {
    const bool odd  = (i & 1);
    const bool same = (j == i);
    const float s = va + vb;
    float2 first;
    if (!odd) first = same ? make_float2(s, 0.f) : make_float2(va, vb);
    else      first = make_float2(0.f, same ? s : va);
    atomicAdd((float2*)(base + (i & ~1)), first);
    if (odd && !same)
        atomicAdd((float2*)(base + i + 1), make_float2(vb, 0.f));
}

__device__ __forceinline__ void process_sample(const float* __restrict__ x,
                                               float4 r, float v,
                                               float* __restrict__ y) {
    // wf = 1-(r-floor), wc = 1-(ceil-r); matches reference including the
    // frac==0 case (floor==ceil, both weights 1 -> double count).
    float f0 = floorf(r.x), c0 = ceilf(r.x);
    float wf0 = 1.0f - (r.x - f0), wc0 = 1.0f - (c0 - r.x);
    float f1 = floorf(r.y), c1 = ceilf(r.y);
    float wf1 = 1.0f - (r.y - f1), wc1 = 1.0f - (c1 - r.y);
    float f2 = floorf(r.z), c2 = ceilf(r.z);
    float wf2 = 1.0f - (r.z - f2), wc2 = 1.0f - (c2 - r.z);
    float f3 = floorf(r.w), c3 = ceilf(r.w);
    float wf3 = 1.0f - (r.w - f3), wc3 = 1.0f - (c3 - r.w);

    int if0 = (int)f0, ic0 = (int)c0;
    int if1 = (int)f1, ic1 = (int)c1;
    int if2 = (int)f2, ic2 = (int)c2;
    int if3 = (int)f3, ic3 = (int)c3;

    float xff, xfc, xcf, xcc;
    gather_pair(x + (long)if0 * DIM, if1, ic1, xff, xfc);
    gather_pair(x + (long)ic0 * DIM, if1, ic1, xcf, xcc);

    float G = wf0 * (wf1 * xff + wc1 * xfc)
            + wc0 * (wf1 * xcf + wc1 * xcc);
    float gv = G * v;

    scatter_pair(y + (long)if2 * DIM, if3, ic3, gv * wf2 * wf3, gv * wf2 * wc3);
    scatter_pair(y + (long)ic2 * DIM, if3, ic3, gv * wc2 * wf3, gv * wc2 * wc3);
}

#define SPT 4   // samples per thread

__global__ void __launch_bounds__(256) hyper_main_kernel(
    const float* __restrict__ x,
    const float4* __restrict__ ri,   // [N] of (r0,r1,r2,r3)
    const float* __restrict__ rv,    // [N]
    float* __restrict__ y,
    int N, int T)                    // T = threads doing work; samples tid + k*T
{
    int tid = blockIdx.x * blockDim.x + threadIdx.x;
    if (tid >= T) return;

    float4 r[SPT];
    float  v[SPT];
    bool   has[SPT];

    // Batch the index/value loads up front for MLP.
    #pragma unroll
    for (int k = 0; k < SPT; k++) {
        int n = tid + k * T;
        has[k] = (n < N);
        if (has[k]) { r[k] = ri[n]; v[k] = rv[n]; }
    }

    #pragma unroll
    for (int k = 0; k < SPT; k++) {
        if (has[k]) process_sample(x, r[k], v[k], y);
    }
}

extern "C" void kernel_launch(void* const* d_in, const int* in_sizes, int n_in,
                              void* d_out, int out_size) {
    const float*  x  = (const float*)d_in[0];   // 1024*1024
    const float4* ri = (const float4*)d_in[1];  // N x float4
    const float*  rv = (const float*)d_in[2];   // N
    float*        y  = (float*)d_out;           // 1024*1024

    int N = in_sizes[2];

    int n4 = out_size / 4;
    hyper_zero_kernel<<<(n4 + 255) / 256, 256>>>((float4*)y, n4);

    int T = (N + SPT - 1) / SPT;         // SPT samples per thread
    int blocks = (T + 255) / 256;
    hyper_main_kernel<<<blocks, 256>>>(x, ri, rv, y, N, T);
}

// round 17
// speedup vs baseline: 1.0152x; 1.0017x over previous
#include <cuda_runtime.h>
#include <cuda_bf16.h>
#include <cstdint>

// HyperLayer multilinear gather/scatter, factorized:
//   G = bilinear gather from x over (dim0,dim1); y[o2,o3] += v*G*w2*w3 over 4 combos.
// R14: fully branchless pair gather/scatter (aligned float2 + predicated second
// op, no BSSY) so ptxas can batch loads; 4 samples/thread for MLP.

#define DIM 1024

__global__ void hyper_zero_kernel(float4* __restrict__ y, int n4) {
    int i = blockIdx.x * blockDim.x + threadIdx.x;
    if (i < n4) y[i] = make_float4(0.f, 0.f, 0.f, 0.f);
}

__device__ __forceinline__ float2 ldg2(const float* p) {
    return __ldg((const float2*)p);
}

// Branchless gather of base[i], base[j] where j==i or j==i+1.
// One aligned float2 load always; predicated second load only when the pair
// straddles an alignment boundary (odd i with j==i+1).
__device__ __forceinline__ void gather_pair(const float* __restrict__ base,
                                            int i, int j, float& a, float& b) {
    const float2 p = ldg2(base + (i & ~1));
    const bool odd  = (i & 1);
    const bool sec  = odd && (j != i);      // need element at j=i+1 (even)
    a = odd ? p.y : p.x;
    float qx = 0.f;
    if (sec) qx = ldg2(base + j).x;         // predicated, j aligned
    b = sec ? qx : ((j == i) ? a : p.y);
}

// Branchless scatter-add va->base[i], vb->base[j] (j==i or j==i+1).
// Always one aligned float2 atomic (untouched lane gets +0.0f, exact no-op);
// predicated second atomic only for odd i with distinct j.
// j==i collapses to a single add of (va+vb) == reference double-count.
__device__ __forceinline__ void scatter_pair(float* __restrict__ base,
                                             int i, int j, float va, float vb) {
    const bool odd  = (i & 1);
    const bool same = (j == i);
    const float s = va + vb;
    float2 first;
    if (!odd) first = same ? make_float2(s, 0.f) : make_float2(va, vb);
    else      first = make_float2(0.f, same ? s : va);
    atomicAdd((float2*)(base + (i & ~1)), first);
    if (odd && !same)
        atomicAdd((float2*)(base + i + 1), make_float2(vb, 0.f));
}

__device__ __forceinline__ void process_sample(const float* __restrict__ x,
                                               float4 r, float v,
                                               float* __restrict__ y) {
    // wf = 1-(r-floor), wc = 1-(ceil-r); matches reference including the
    // frac==0 case (floor==ceil, both weights 1 -> double count).
    float f0 = floorf(r.x), c0 = ceilf(r.x);
    float wf0 = 1.0f - (r.x - f0), wc0 = 1.0f - (c0 - r.x);
    float f1 = floorf(r.y), c1 = ceilf(r.y);
    float wf1 = 1.0f - (r.y - f1), wc1 = 1.0f - (c1 - r.y);
    float f2 = floorf(r.z), c2 = ceilf(r.z);
    float wf2 = 1.0f - (r.z - f2), wc2 = 1.0f - (c2 - r.z);
    float f3 = floorf(r.w), c3 = ceilf(r.w);
    float wf3 = 1.0f - (r.w - f3), wc3 = 1.0f - (c3 - r.w);

    int if0 = (int)f0, ic0 = (int)c0;
    int if1 = (int)f1, ic1 = (int)c1;
    int if2 = (int)f2, ic2 = (int)c2;
    int if3 = (int)f3, ic3 = (int)c3;

    float xff, xfc, xcf, xcc;
    gather_pair(x + (long)if0 * DIM, if1, ic1, xff, xfc);
    gather_pair(x + (long)ic0 * DIM, if1, ic1, xcf, xcc);

    float G = wf0 * (wf1 * xff + wc1 * xfc)
            + wc0 * (wf1 * xcf + wc1 * xcc);
    float gv = G * v;

    scatter_pair(y + (long)if2 * DIM, if3, ic3, gv * wf2 * wf3, gv * wf2 * wc3);
    scatter_pair(y + (long)ic2 * DIM, if3, ic3, gv * wc2 * wf3, gv * wc2 * wc3);
}

#define SPT 4   // samples per thread

__global__ void __launch_bounds__(256) hyper_main_kernel(
    const float* __restrict__ x,
    const float4* __restrict__ ri,   // [N] of (r0,r1,r2,r3)
    const float* __restrict__ rv,    // [N]
    float* __restrict__ y,
    int N, int T)                    // T = threads doing work; samples tid + k*T
{
    int tid = blockIdx.x * blockDim.x + threadIdx.x;
    if (tid >= T) return;

    float4 r[SPT];
    float  v[SPT];
    bool   has[SPT];

    // Batch the index/value loads up front for MLP.
    #pragma unroll
    for (int k = 0; k < SPT; k++) {
        int n = tid + k * T;
        has[k] = (n < N);
        if (has[k]) { r[k] = ri[n]; v[k] = rv[n]; }
    }

    #pragma unroll
    for (int k = 0; k < SPT; k++) {
        if (has[k]) process_sample(x, r[k], v[k], y);
    }
}

extern "C" void kernel_launch(void* const* d_in, const int* in_sizes, int n_in,
                              void* d_out, int out_size) {
    const float*  x  = (const float*)d_in[0];   // 1024*1024
    const float4* ri = (const float4*)d_in[1];  // N x float4
    const float*  rv = (const float*)d_in[2];   // N
    float*        y  = (float*)d_out;           // 1024*1024

    int N = in_sizes[2];

    int n4 = out_size / 4;
    hyper_zero_kernel<<<(n4 + 255) / 256, 256>>>((float4*)y, n4);

    int T = (N + SPT - 1) / SPT;         // SPT samples per thread
    int blocks = (T + 255) / 256;
    hyper_main_kernel<<<blocks, 256>>>(x, ri, rv, y, N, T);
}